// round 9
// baseline (speedup 1.0000x reference)
#include <cuda_runtime.h>
#include <math.h>

// ---------------------------------------------------------------------------
// MS-SSIM + L1 loss — single fused kernel, R4 compute structure,
// 2 x 256-thread blocks per SM (independent barrier domains).
//
// Tile: 64 wide x 32 tall output; slab 96 x 64 (x,y denormalized) in smem.
// Per (channel, sigma) combo:
//   hpassP/vpassP : packed (v, v^2) 1-D convs via fma.rn.f32x2 -> mu, E[v^2]
//   carrier combo : packed (x*y, |x-y|) dual conv (per-lane coefs sigma / s4)
//   other combos  : scalar xy conv
// SSIM pointwise with immediate fold, block reduction; last block to finish
// computes disc MSE + deterministic final combine (self-resetting counter).
// Coefs are host-computed (identical fp32 formula to the reference) and passed
// as a __grid_constant__ parameter (constant bank, no smem aliasing).
//
// Combos: c0: (s0,r3)x3, (s1,r6)x2[carrier]
//         c1: (s1,r6)x1, (s2,r11)x3, (s3,r16)x1[carrier]
//         c2: (s3,r16)x2, (s4,r16)x3 + l^3 [carrier]
// ---------------------------------------------------------------------------

typedef unsigned long long u64;

#define TH 32     // output tile height
#define SH 64     // slab / intermediate height (TH + 32)
#define W2 97     // slab row stride (floats); 97 % 32 == 1 -> conflict-free
#define WT 65     // scalar tmp row stride (floats)
#define WTU 65    // packed tmp row stride (u64)
#define NT 256    // threads per block
#define NSLOT 512 // h-pass slots: SH rows x 8 col-groups
#define SMEM_BYTES (2 * SH * W2 * 4 + SH * WTU * 8)   // 49664+33280 = 82944
#define NBLK 1024

struct Coefs { float g[5][33]; };

__device__ float g_partLoss[NBLK];
__device__ float g_partL1[NBLK];
__device__ int g_counter;   // zero-init; self-reset each launch

// ---------------------------------------------------------------------------
__device__ __forceinline__ u64 pk2(float lo, float hi) {
    u64 r; asm("mov.b64 %0, {%1, %2};" : "=l"(r) : "f"(lo), "f"(hi)); return r;
}
__device__ __forceinline__ void upk2(u64 v, float& lo, float& hi) {
    asm("mov.b64 {%0, %1}, %2;" : "=f"(lo), "=f"(hi) : "l"(v));
}
__device__ __forceinline__ u64 ffma2(u64 a, u64 b, u64 c) {
    u64 d; asm("fma.rn.f32x2 %0, %1, %2, %3;" : "=l"(d) : "l"(a), "l"(b), "l"(c));
    return d;
}

// ---------------------------------------------------------------------------
// Packed (v, v^2) horizontal conv. NSLOT slots = SH rows x 8 col-groups.
template <int R>
__device__ __forceinline__ void hpassP(const float* __restrict__ s, u64* t2,
                                       const float* __restrict__ g1, int tid) {
    for (int idx = tid; idx < NSLOT; idx += NT) {
        int r = idx % SH, gq = idx / SH;
        const float* p = s + r * W2 + gq * 8 + (16 - R);
        u64 acc[8], w[8];
#pragma unroll
        for (int j = 0; j < 8; j++) { float f = p[j]; w[j] = pk2(f, f * f); }
#pragma unroll
        for (int i = 0; i < 8; i++) acc[i] = 0ULL;
#pragma unroll
        for (int k = 0; k <= 2 * R; k++) {
            float gk = g1[k];
            u64 c2 = pk2(gk, gk);
#pragma unroll
            for (int i = 0; i < 8; i++) acc[i] = ffma2(c2, w[(k + i) & 7], acc[i]);
            if (k < 2 * R) { float f = p[k + 8]; w[k & 7] = pk2(f, f * f); }
        }
        u64* ob = t2 + r * WTU + gq * 8;
#pragma unroll
        for (int i = 0; i < 8; i++) ob[i] = acc[i];
    }
}

// Packed vertical conv. NT threads = 64 cols x 4 row-groups of 8.
template <int R>
__device__ __forceinline__ void vpassP(const u64* t2, const float* __restrict__ g1,
                                       int tx, int ty, u64 out[8]) {
    const u64* p = t2 + (ty * 8 + 16 - R) * WTU + tx;
    u64 acc[8], w[8];
#pragma unroll
    for (int j = 0; j < 8; j++) w[j] = p[j * WTU];
#pragma unroll
    for (int i = 0; i < 8; i++) acc[i] = 0ULL;
#pragma unroll
    for (int k = 0; k <= 2 * R; k++) {
        float gk = g1[k];
        u64 c2 = pk2(gk, gk);
#pragma unroll
        for (int i = 0; i < 8; i++) acc[i] = ffma2(c2, w[(k + i) & 7], acc[i]);
        if (k < 2 * R) w[k & 7] = p[(k + 8) * WTU];
    }
#pragma unroll
    for (int i = 0; i < 8; i++) out[i] = acc[i];
}

// Dual (x*y, |x-y|) horizontal conv at full 33-tap window; per-lane coefs.
__device__ __forceinline__ void hpassXY(const float* sx, const float* sy, u64* t2,
                                        const float* __restrict__ gA,
                                        const float* __restrict__ gB, int tid) {
    for (int idx = tid; idx < NSLOT; idx += NT) {
        int r = idx % SH, gq = idx / SH;
        const float* px = sx + r * W2 + gq * 8;
        const float* py = sy + r * W2 + gq * 8;
        u64 acc[8], w[8];
#pragma unroll
        for (int j = 0; j < 8; j++) {
            float xv = px[j], yv = py[j];
            w[j] = pk2(xv * yv, fabsf(xv - yv));
        }
#pragma unroll
        for (int i = 0; i < 8; i++) acc[i] = 0ULL;
#pragma unroll
        for (int k = 0; k <= 32; k++) {
            u64 c2 = pk2(gA[k], gB[k]);
#pragma unroll
            for (int i = 0; i < 8; i++) acc[i] = ffma2(c2, w[(k + i) & 7], acc[i]);
            if (k < 32) {
                float xv = px[k + 8], yv = py[k + 8];
                w[k & 7] = pk2(xv * yv, fabsf(xv - yv));
            }
        }
        u64* ob = t2 + r * WTU + gq * 8;
#pragma unroll
        for (int i = 0; i < 8; i++) ob[i] = acc[i];
    }
}

__device__ __forceinline__ void vpassXY(const u64* t2,
                                        const float* __restrict__ gA,
                                        const float* __restrict__ gB,
                                        int tx, int ty, u64 out[8]) {
    const u64* p = t2 + ty * 8 * WTU + tx;
    u64 acc[8], w[8];
#pragma unroll
    for (int j = 0; j < 8; j++) w[j] = p[j * WTU];
#pragma unroll
    for (int i = 0; i < 8; i++) acc[i] = 0ULL;
#pragma unroll
    for (int k = 0; k <= 32; k++) {
        u64 c2 = pk2(gA[k], gB[k]);
#pragma unroll
        for (int i = 0; i < 8; i++) acc[i] = ffma2(c2, w[(k + i) & 7], acc[i]);
        if (k < 32) w[k & 7] = p[(k + 8) * WTU];
    }
#pragma unroll
    for (int i = 0; i < 8; i++) out[i] = acc[i];
}

// Scalar xy conv (non-carrier combos).
template <int R>
__device__ __forceinline__ void hpassS(const float* sx, const float* sy, float* t0,
                                       const float* __restrict__ g1, int tid) {
    for (int idx = tid; idx < NSLOT; idx += NT) {
        int r = idx % SH, gq = idx / SH;
        const float* px = sx + r * W2 + gq * 8 + (16 - R);
        const float* py = sy + r * W2 + gq * 8 + (16 - R);
        float acc[8], w[8];
#pragma unroll
        for (int j = 0; j < 8; j++) w[j] = px[j] * py[j];
#pragma unroll
        for (int i = 0; i < 8; i++) acc[i] = 0.0f;
#pragma unroll
        for (int k = 0; k <= 2 * R; k++) {
            float gk = g1[k];
#pragma unroll
            for (int i = 0; i < 8; i++) acc[i] = fmaf(gk, w[(k + i) & 7], acc[i]);
            if (k < 2 * R) w[k & 7] = px[k + 8] * py[k + 8];
        }
        float* ob = t0 + r * WT + gq * 8;
#pragma unroll
        for (int i = 0; i < 8; i++) ob[i] = acc[i];
    }
}

template <int R>
__device__ __forceinline__ void vpassS(const float* t0, const float* __restrict__ g1,
                                       int tx, int ty, float out[8]) {
    const float* p = t0 + (ty * 8 + 16 - R) * WT + tx;
    float acc[8], w[8];
#pragma unroll
    for (int j = 0; j < 8; j++) w[j] = p[j * WT];
#pragma unroll
    for (int i = 0; i < 8; i++) acc[i] = 0.0f;
#pragma unroll
    for (int k = 0; k <= 2 * R; k++) {
        float gk = g1[k];
#pragma unroll
        for (int i = 0; i < 8; i++) acc[i] = fmaf(gk, w[(k + i) & 7], acc[i]);
        if (k < 2 * R) w[k & 7] = p[(k + 8) * WT];
    }
#pragma unroll
    for (int i = 0; i < 8; i++) out[i] = acc[i];
}

// ---------------------------------------------------------------------------
template <int R, bool CARRIER>
__device__ __forceinline__ void comboP(const float* __restrict__ gs,
                                       const float* __restrict__ g4,
                                       int mult, bool lm,
                                       const float* sx, const float* sy,
                                       u64* t2, int tid, int tx, int ty,
                                       float prod[8], float l1s[8]) {
    const float* g1 = gs + (16 - R);
    u64 o1[8], o2[8];
    float exy[8];

    hpassP<R>(sx, t2, g1, tid);
    __syncthreads();
    vpassP<R>(t2, g1, tx, ty, o1);
    __syncthreads();
    hpassP<R>(sy, t2, g1, tid);
    __syncthreads();
    vpassP<R>(t2, g1, tx, ty, o2);
    __syncthreads();

    if (CARRIER) {
        u64 o3[8];
        hpassXY(sx, sy, t2, gs, g4, tid);
        __syncthreads();
        vpassXY(t2, gs, g4, tx, ty, o3);
        __syncthreads();
#pragma unroll
        for (int i = 0; i < 8; i++) {
            float lv;
            upk2(o3[i], exy[i], lv);
            l1s[i] += lv;
        }
    } else {
        float* t0 = (float*)t2;
        hpassS<R>(sx, sy, t0, g1, tid);
        __syncthreads();
        vpassS<R>(t0, g1, tx, ty, exy);
        __syncthreads();
    }

#pragma unroll
    for (int i = 0; i < 8; i++) {
        float mux, ex2, muy, ey2;
        upk2(o1[i], mux, ex2);
        upk2(o2[i], muy, ey2);
        float m2x = mux * mux, m2y = muy * muy, mxy = mux * muy;
        float sxx = ex2 - m2x, syy = ey2 - m2y, sxyv = exy[i] - mxy;
        float cs = __fdividef(2.0f * sxyv + 9.0e-4f, sxx + syy + 9.0e-4f);
        float m = cs;
        if (mult >= 2) m *= cs;
        if (mult >= 3) m *= cs;
        if (lm) {
            float l = __fdividef(2.0f * mxy + 1.0e-4f, m2x + m2y + 1.0e-4f);
            m *= l * l * l;
        }
        prod[i] *= m;
    }
}

// ---------------------------------------------------------------------------
__global__ __launch_bounds__(NT, 2) void fusedK(const float* __restrict__ x,
                                                const float* __restrict__ y,
                                                const float* __restrict__ disc,
                                                int ndisc, float* __restrict__ out,
                                                const __grid_constant__ Coefs cf) {
    extern __shared__ float smem[];
    float* sx = smem;                    // SH x W2
    float* sy = sx + SH * W2;
    u64* t2 = (u64*)(sy + SH * W2);      // SH x WTU u64

    int tid = threadIdx.x;
    int tx = tid & 63, ty = tid >> 6;    // 64 cols x 4 row-groups
    int col0 = blockIdx.x * 64, row0 = blockIdx.y * TH, b = blockIdx.z;

    float prod[8], l1s[8];
#pragma unroll
    for (int i = 0; i < 8; i++) { prod[i] = 1.0f; l1s[i] = 0.0f; }
    float rawL1 = 0.0f;

    for (int c = 0; c < 3; c++) {
        const float* xp = x + (size_t)(b * 3 + c) * 262144;
        const float* yp = y + (size_t)(b * 3 + c) * 262144;
        __syncthreads();
        for (int idx = tid; idx < SH * 96; idx += NT) {
            int rr = idx / 96, cc = idx - rr * 96;
            int gr = row0 - 16 + rr, gc = col0 - 16 + cc;
            float xv = 0.0f, yv = 0.0f;
            if (gr >= 0 && gr < 512 && gc >= 0 && gc < 512) {
                xv = fmaf(xp[gr * 512 + gc], 0.5f, 0.5f);
                yv = fmaf(yp[gr * 512 + gc], 0.5f, 0.5f);
            }
            sx[rr * W2 + cc] = xv;
            sy[rr * W2 + cc] = yv;
            if (rr >= 16 && rr < 16 + TH && cc >= 16 && cc < 80)
                rawL1 += fabsf(xv - yv);
        }
        __syncthreads();

        if (c == 0) {
            comboP<3, false>(cf.g[0], cf.g[4], 3, false, sx, sy, t2, tid, tx, ty, prod, l1s);
            comboP<6, true>(cf.g[1], cf.g[4], 2, false, sx, sy, t2, tid, tx, ty, prod, l1s);
        } else if (c == 1) {
            comboP<6, false>(cf.g[1], cf.g[4], 1, false, sx, sy, t2, tid, tx, ty, prod, l1s);
            comboP<11, false>(cf.g[2], cf.g[4], 3, false, sx, sy, t2, tid, tx, ty, prod, l1s);
            comboP<16, true>(cf.g[3], cf.g[4], 1, false, sx, sy, t2, tid, tx, ty, prod, l1s);
        } else {
            comboP<16, false>(cf.g[3], cf.g[4], 2, false, sx, sy, t2, tid, tx, ty, prod, l1s);
            comboP<16, true>(cf.g[4], cf.g[4], 3, true, sx, sy, t2, tid, tx, ty, prod, l1s);
        }
    }

    float tsum = 0.0f;
#pragma unroll
    for (int i = 0; i < 8; i++) {
        float ms = 1.0f - prod[i];
        float mix = 200.0f * (0.025f * ms + 0.975f * (l1s[i] * (1.0f / 3.0f)));
        tsum += mix;
    }

    // Block reduction into partials.
    __syncthreads();
    float* r1 = (float*)t2;
    float* r2 = r1 + NT;
    r1[tid] = tsum;
    r2[tid] = rawL1;
    __syncthreads();
    for (int s = NT / 2; s > 0; s >>= 1) {
        if (tid < s) { r1[tid] += r1[tid + s]; r2[tid] += r2[tid + s]; }
        __syncthreads();
    }
    int bid = (blockIdx.z * 16 + blockIdx.y) * 8 + blockIdx.x;
    if (tid == 0) {
        g_partLoss[bid] = r1[0];
        g_partL1[bid] = r2[0];
    }

    // --- last block to finish computes the final scalar ---
    __shared__ int isLast;
    __threadfence();
    if (tid == 0) isLast = (atomicAdd(&g_counter, 1) == NBLK - 1) ? 1 : 0;
    __syncthreads();
    if (!isLast) return;
    __threadfence();   // acquire: all blocks' partials visible

    float ms = 0.0f;
    for (int i = tid; i < ndisc; i += NT) {
        float v = disc[i] - 1.0f;
        ms = fmaf(v, v, ms);
    }
    double s1 = 0.0, s2 = 0.0;
#pragma unroll
    for (int q = 0; q < NBLK / NT; q++) {      // fixed order -> deterministic
        s1 += (double)g_partLoss[tid + q * NT];
        s2 += (double)g_partL1[tid + q * NT];
    }

    double* d1 = (double*)t2;            // reuse smem
    double* d2 = d1 + NT;
    float* d3 = (float*)(d2 + NT);
    __syncthreads();
    d1[tid] = s1; d2[tid] = s2; d3[tid] = ms;
    __syncthreads();
    for (int s = NT / 2; s > 0; s >>= 1) {
        if (tid < s) {
            d1[tid] += d1[tid + s];
            d2[tid] += d2[tid + s];
            d3[tid] += d3[tid + s];
        }
        __syncthreads();
    }
    if (tid == 0) {
        double lossMixMean = d1[0] / 2097152.0;     // 8*512*512
        double l1Mean = d2[0] / 6291456.0;          // 8*3*512*512
        double mseMean = (double)d3[0] / (double)ndisc;
        out[0] = (float)((lossMixMean + 100.0 * l1Mean + mseMean) * 0.5);
        g_counter = 0;                    // reset for next graph replay
        __threadfence();
    }
}

// ---------------------------------------------------------------------------
extern "C" void kernel_launch(void* const* d_in, const int* in_sizes, int n_in,
                              void* d_out, int out_size) {
    const float* x = (const float*)d_in[0];
    const float* y = (const float*)d_in[1];
    const float* disc = (const float*)d_in[2];
    int ndisc = in_sizes[2];

    // Host-side 1-D Gaussian coefs, float32 math mirroring _build_g_masks.
    static const float sigmas[5] = {0.5f, 1.0f, 2.0f, 4.0f, 8.0f};
    Coefs cf;
    for (int s = 0; s < 5; s++) {
        float sum = 0.0f;
        for (int i = 0; i < 33; i++) {
            float d = (float)(i - 16);
            float v = expf(-d * d / (2.0f * sigmas[s] * sigmas[s]));
            cf.g[s][i] = v;
            sum += v;
        }
        for (int i = 0; i < 33; i++) cf.g[s][i] /= sum;
    }

    cudaFuncSetAttribute(fusedK, cudaFuncAttributeMaxDynamicSharedMemorySize,
                         SMEM_BYTES);
    fusedK<<<dim3(8, 16, 8), NT, SMEM_BYTES>>>(x, y, disc, ndisc,
                                               (float*)d_out, cf);
}

// round 10
// speedup vs baseline: 1.0720x; 1.0720x over previous
#include <cuda_runtime.h>
#include <math.h>

// ---------------------------------------------------------------------------
// MS-SSIM + L1 loss — single fused kernel; R4 geometry (64x64 tile, 512 thr,
// 96-row slab) with every barrier phase exactly load-balanced:
//  - P-passes (x & y of one sigma) paired into one 1536-slot phase (3/thread)
//  - c1 xy(s1)+xy(s2) paired; c2 xy(s3)+carrierXY(s4) paired (both 33-tap)
//  - unequal pairs (c0 carrierXY+xy@s0) and the lone c1 carrierXY use
//    4-col-group slots with block-of-512 type interleave (per-thread uniform)
//  - prod/l1s accumulators live in smem (frees 16 persistent registers)
// Last block to finish does disc MSE + deterministic final combine.
// Coefs host-computed (identical fp32 formula) in a __grid_constant__ param.
// ---------------------------------------------------------------------------

typedef unsigned long long u64;

#define W2 97     // slab row stride (floats)
#define WTU 65    // tmp row stride (u64 / float elements)
#define NT 512
#define NBLK 512

// smem layout (floats):
// tA u64[96*65]=12480f | tB 12480f | sx 9312 | sy 9312 | prodS 4096 | l1sS 4096
#define OFF_TA 0
#define OFF_TB 12480
#define OFF_SX 24960
#define OFF_SY 34272
#define OFF_PR 43584
#define OFF_L1 47680
#define SMEM_BYTES (51776 * 4)

struct Coefs { float g[5][33]; };

__device__ float g_partLoss[NBLK];
__device__ float g_partL1[NBLK];
__device__ int g_counter;

// ---------------------------------------------------------------------------
__device__ __forceinline__ u64 pk2(float lo, float hi) {
    u64 r; asm("mov.b64 %0, {%1, %2};" : "=l"(r) : "f"(lo), "f"(hi)); return r;
}
__device__ __forceinline__ void upk2(u64 v, float& lo, float& hi) {
    asm("mov.b64 {%0, %1}, %2;" : "=f"(lo), "=f"(hi) : "l"(v));
}
__device__ __forceinline__ u64 ffma2(u64 a, u64 b, u64 c) {
    u64 d; asm("fma.rn.f32x2 %0, %1, %2, %3;" : "=l"(d) : "l"(a), "l"(b), "l"(c));
    return d;
}

// ---------------------------------------------------------------------------
// h slot bodies. grp8 slot in [0,768): 96 rows x 8 col-groups of 8.
// grp4 slot in [0,1536): 96 rows x 16 col-groups of 4.

template <int R>
__device__ __forceinline__ void hPslot(int slot, const float* __restrict__ s,
                                       u64* t, const float* __restrict__ g1) {
    int r = slot % 96, gq = slot / 96;
    const float* p = s + r * W2 + gq * 8 + (16 - R);
    u64 acc[8], w[8];
#pragma unroll
    for (int j = 0; j < 8; j++) { float f = p[j]; w[j] = pk2(f, f * f); }
#pragma unroll
    for (int i = 0; i < 8; i++) acc[i] = 0ULL;
#pragma unroll
    for (int k = 0; k <= 2 * R; k++) {
        float gk = g1[k];
        u64 c2 = pk2(gk, gk);
#pragma unroll
        for (int i = 0; i < 8; i++) acc[i] = ffma2(c2, w[(k + i) & 7], acc[i]);
        if (k < 2 * R) { float f = p[k + 8]; w[k & 7] = pk2(f, f * f); }
    }
    u64* ob = t + r * WTU + gq * 8;
#pragma unroll
    for (int i = 0; i < 8; i++) ob[i] = acc[i];
}

template <int R>
__device__ __forceinline__ void hSslot(int slot, const float* sx, const float* sy,
                                       float* t0, const float* __restrict__ g1) {
    int r = slot % 96, gq = slot / 96;
    const float* px = sx + r * W2 + gq * 8 + (16 - R);
    const float* py = sy + r * W2 + gq * 8 + (16 - R);
    float acc[8], w[8];
#pragma unroll
    for (int j = 0; j < 8; j++) w[j] = px[j] * py[j];
#pragma unroll
    for (int i = 0; i < 8; i++) acc[i] = 0.0f;
#pragma unroll
    for (int k = 0; k <= 2 * R; k++) {
        float gk = g1[k];
#pragma unroll
        for (int i = 0; i < 8; i++) acc[i] = fmaf(gk, w[(k + i) & 7], acc[i]);
        if (k < 2 * R) w[k & 7] = px[k + 8] * py[k + 8];
    }
    float* ob = t0 + r * WTU + gq * 8;
#pragma unroll
    for (int i = 0; i < 8; i++) ob[i] = acc[i];
}

__device__ __forceinline__ void hXYslot(int slot, const float* sx, const float* sy,
                                        u64* t, const float* __restrict__ gA,
                                        const float* __restrict__ gB) {
    int r = slot % 96, gq = slot / 96;
    const float* px = sx + r * W2 + gq * 8;
    const float* py = sy + r * W2 + gq * 8;
    u64 acc[8], w[8];
#pragma unroll
    for (int j = 0; j < 8; j++) {
        float xv = px[j], yv = py[j];
        w[j] = pk2(xv * yv, fabsf(xv - yv));
    }
#pragma unroll
    for (int i = 0; i < 8; i++) acc[i] = 0ULL;
#pragma unroll
    for (int k = 0; k <= 32; k++) {
        u64 c2 = pk2(gA[k], gB[k]);
#pragma unroll
        for (int i = 0; i < 8; i++) acc[i] = ffma2(c2, w[(k + i) & 7], acc[i]);
        if (k < 32) {
            float xv = px[k + 8], yv = py[k + 8];
            w[k & 7] = pk2(xv * yv, fabsf(xv - yv));
        }
    }
    u64* ob = t + r * WTU + gq * 8;
#pragma unroll
    for (int i = 0; i < 8; i++) ob[i] = acc[i];
}

__device__ __forceinline__ void hXYslot4(int slot, const float* sx, const float* sy,
                                         u64* t, const float* __restrict__ gA,
                                         const float* __restrict__ gB) {
    int r = slot % 96, gq = slot / 96;
    const float* px = sx + r * W2 + gq * 4;
    const float* py = sy + r * W2 + gq * 4;
    u64 acc[4], w[8];
#pragma unroll
    for (int j = 0; j < 4; j++) {
        float xv = px[j], yv = py[j];
        w[j] = pk2(xv * yv, fabsf(xv - yv));
    }
#pragma unroll
    for (int i = 0; i < 4; i++) acc[i] = 0ULL;
#pragma unroll
    for (int k = 0; k <= 32; k++) {
        u64 c2 = pk2(gA[k], gB[k]);
#pragma unroll
        for (int i = 0; i < 4; i++) acc[i] = ffma2(c2, w[(k + i) & 7], acc[i]);
        if (k < 32) {
            float xv = px[k + 4], yv = py[k + 4];
            w[(k + 4) & 7] = pk2(xv * yv, fabsf(xv - yv));
        }
    }
    u64* ob = t + r * WTU + gq * 4;
#pragma unroll
    for (int i = 0; i < 4; i++) ob[i] = acc[i];
}

template <int R>
__device__ __forceinline__ void hSslot4(int slot, const float* sx, const float* sy,
                                        float* t0, const float* __restrict__ g1) {
    int r = slot % 96, gq = slot / 96;
    const float* px = sx + r * W2 + gq * 4 + (16 - R);
    const float* py = sy + r * W2 + gq * 4 + (16 - R);
    float acc[4], w[8];
#pragma unroll
    for (int j = 0; j < 4; j++) w[j] = px[j] * py[j];
#pragma unroll
    for (int i = 0; i < 4; i++) acc[i] = 0.0f;
#pragma unroll
    for (int k = 0; k <= 2 * R; k++) {
        float gk = g1[k];
#pragma unroll
        for (int i = 0; i < 4; i++) acc[i] = fmaf(gk, w[(k + i) & 7], acc[i]);
        if (k < 2 * R) w[(k + 4) & 7] = px[k + 4] * py[k + 4];
    }
    float* ob = t0 + r * WTU + gq * 4;
#pragma unroll
    for (int i = 0; i < 4; i++) ob[i] = acc[i];
}

// ---------------------------------------------------------------------------
// v passes: 512 threads = 64 cols x 8 row-groups of 8.
template <int R>
__device__ __forceinline__ void vpassP(const u64* t2, const float* __restrict__ g1,
                                       int tx, int ty, u64 out[8]) {
    const u64* p = t2 + (ty * 8 + 16 - R) * WTU + tx;
    u64 acc[8], w[8];
#pragma unroll
    for (int j = 0; j < 8; j++) w[j] = p[j * WTU];
#pragma unroll
    for (int i = 0; i < 8; i++) acc[i] = 0ULL;
#pragma unroll
    for (int k = 0; k <= 2 * R; k++) {
        float gk = g1[k];
        u64 c2 = pk2(gk, gk);
#pragma unroll
        for (int i = 0; i < 8; i++) acc[i] = ffma2(c2, w[(k + i) & 7], acc[i]);
        if (k < 2 * R) w[k & 7] = p[(k + 8) * WTU];
    }
#pragma unroll
    for (int i = 0; i < 8; i++) out[i] = acc[i];
}

__device__ __forceinline__ void vpassXY(const u64* t2,
                                        const float* __restrict__ gA,
                                        const float* __restrict__ gB,
                                        int tx, int ty, u64 out[8]) {
    const u64* p = t2 + ty * 8 * WTU + tx;
    u64 acc[8], w[8];
#pragma unroll
    for (int j = 0; j < 8; j++) w[j] = p[j * WTU];
#pragma unroll
    for (int i = 0; i < 8; i++) acc[i] = 0ULL;
#pragma unroll
    for (int k = 0; k <= 32; k++) {
        u64 c2 = pk2(gA[k], gB[k]);
#pragma unroll
        for (int i = 0; i < 8; i++) acc[i] = ffma2(c2, w[(k + i) & 7], acc[i]);
        if (k < 32) w[k & 7] = p[(k + 8) * WTU];
    }
#pragma unroll
    for (int i = 0; i < 8; i++) out[i] = acc[i];
}

template <int R>
__device__ __forceinline__ void vpassS(const float* t0, const float* __restrict__ g1,
                                       int tx, int ty, float out[8]) {
    const float* p = t0 + (ty * 8 + 16 - R) * WTU + tx;
    float acc[8], w[8];
#pragma unroll
    for (int j = 0; j < 8; j++) w[j] = p[j * WTU];
#pragma unroll
    for (int i = 0; i < 8; i++) acc[i] = 0.0f;
#pragma unroll
    for (int k = 0; k <= 2 * R; k++) {
        float gk = g1[k];
#pragma unroll
        for (int i = 0; i < 8; i++) acc[i] = fmaf(gk, w[(k + i) & 7], acc[i]);
        if (k < 2 * R) w[k & 7] = p[(k + 8) * WTU];
    }
#pragma unroll
    for (int i = 0; i < 8; i++) out[i] = acc[i];
}

// ---------------------------------------------------------------------------
__global__ __launch_bounds__(NT) void fusedK(const float* __restrict__ x,
                                             const float* __restrict__ y,
                                             const float* __restrict__ disc,
                                             int ndisc, float* __restrict__ out,
                                             const __grid_constant__ Coefs cf) {
    extern __shared__ float smem[];
    u64* tA = (u64*)(smem + OFF_TA);
    u64* tB = (u64*)(smem + OFF_TB);
    float* tAf = smem + OFF_TA;
    float* tBf = smem + OFF_TB;
    float* sx = smem + OFF_SX;
    float* sy = smem + OFF_SY;
    float* prodS = smem + OFF_PR;
    float* l1sS = smem + OFF_L1;

    int tid = threadIdx.x;
    int tx = tid & 63, ty = tid >> 6;
    int col0 = blockIdx.x * 64, row0 = blockIdx.y * 64, b = blockIdx.z;

    const float* g0 = cf.g[0];
    const float* g1 = cf.g[1];
    const float* g2 = cf.g[2];
    const float* g3 = cf.g[3];
    const float* g4 = cf.g[4];

#pragma unroll
    for (int i = 0; i < 8; i++) {
        prodS[i * NT + tid] = 1.0f;
        l1sS[i * NT + tid] = 0.0f;
    }
    float rawL1 = 0.0f;

    float t1a[8], Sa[8], t1b[8], Sb[8];
    u64 o1[8], o2[8], o3[8];
    float exyA[8], exyB[8];

    auto fold = [&](const u64* ox, const u64* oy, float* t1, float* S, bool lm) {
#pragma unroll
        for (int i = 0; i < 8; i++) {
            float mux, ex2, muy, ey2;
            upk2(ox[i], mux, ex2);
            upk2(oy[i], muy, ey2);
            float m2x = mux * mux, m2y = muy * muy, mxy = mux * muy;
            t1[i] = 9.0e-4f - 2.0f * mxy;
            S[i] = (ex2 - m2x) + (ey2 - m2y) + 9.0e-4f;
            if (lm) {
                float l = __fdividef(2.0f * mxy + 1.0e-4f, m2x + m2y + 1.0e-4f);
                prodS[i * NT + tid] *= l * l * l;
            }
        }
    };
    auto csApply = [&](const float* e, const float* t1, const float* S, int mult) {
#pragma unroll
        for (int i = 0; i < 8; i++) {
            float cs = __fdividef(2.0f * e[i] + t1[i], S[i]);
            float m = cs;
            if (mult >= 2) m *= cs;
            if (mult >= 3) m *= cs;
            prodS[i * NT + tid] *= m;
        }
    };
    auto csApplyCarrier = [&](const u64* o, const float* t1, const float* S,
                              int mult) {
#pragma unroll
        for (int i = 0; i < 8; i++) {
            float e, lv;
            upk2(o[i], e, lv);
            l1sS[i * NT + tid] += lv;
            float cs = __fdividef(2.0f * e + t1[i], S[i]);
            float m = cs;
            if (mult >= 2) m *= cs;
            if (mult >= 3) m *= cs;
            prodS[i * NT + tid] *= m;
        }
    };

    auto loadSlab = [&](int c) {
        const float* xp = x + (size_t)(b * 3 + c) * 262144;
        const float* yp = y + (size_t)(b * 3 + c) * 262144;
        for (int idx = tid; idx < 96 * 96; idx += NT) {
            int rr = idx / 96, cc = idx - rr * 96;
            int gr = row0 - 16 + rr, gc = col0 - 16 + cc;
            float xv = 0.0f, yv = 0.0f;
            if (gr >= 0 && gr < 512 && gc >= 0 && gc < 512) {
                xv = fmaf(xp[gr * 512 + gc], 0.5f, 0.5f);
                yv = fmaf(yp[gr * 512 + gc], 0.5f, 0.5f);
            }
            sx[rr * W2 + cc] = xv;
            sy[rr * W2 + cc] = yv;
            if (rr >= 16 && rr < 80 && cc >= 16 && cc < 80)
                rawL1 += fabsf(xv - yv);
        }
    };

#define HP_PAIR(R, GG)                                                      \
    do {                                                                    \
        _Pragma("unroll")                                                   \
        for (int q = 0; q < 3; q++) {                                       \
            int idx = tid + q * NT;                                         \
            bool isX = idx < 768;                                           \
            hPslot<R>(isX ? idx : idx - 768, isX ? sx : sy,                 \
                      isX ? tA : tB, (GG) + (16 - (R)));                    \
        }                                                                   \
    } while (0)

    // ===================== channel 0 =====================
    loadSlab(0);
    __syncthreads();
    HP_PAIR(3, g0);
    __syncthreads();
    vpassP<3>(tA, g0 + 13, tx, ty, o1);
    vpassP<3>(tB, g0 + 13, tx, ty, o2);
    fold(o1, o2, t1a, Sa, false);
    __syncthreads();
    HP_PAIR(6, g1);
    __syncthreads();
    vpassP<6>(tA, g1 + 10, tx, ty, o1);
    vpassP<6>(tB, g1 + 10, tx, ty, o2);
    fold(o1, o2, t1b, Sb, false);
    __syncthreads();
    // mix grp4: carrierXY(s1)->tB ; xy@s0(R3)->tA. 3072 slots, blk-512 interleave.
#pragma unroll
    for (int q = 0; q < 6; q++) {
        int idx = tid + q * NT;
        int blk = idx >> 9, wv = idx & 511;
        int slot = ((blk >> 1) << 9) | wv;
        if ((blk & 1) == 0) hXYslot4(slot, sx, sy, tB, g1, g4);
        else                hSslot4<3>(slot, sx, sy, tAf, g0 + 13);
    }
    __syncthreads();
    vpassS<3>(tAf, g0 + 13, tx, ty, exyA);
    vpassXY(tB, g1, g4, tx, ty, o3);
    csApply(exyA, t1a, Sa, 3);            // (c0,s0)^3
    csApplyCarrier(o3, t1b, Sb, 2);       // (c0,s1)^2 + L1_c0
    __syncthreads();

    // ===================== channel 1 =====================
    loadSlab(1);
    __syncthreads();
    HP_PAIR(6, g1);
    __syncthreads();
    vpassP<6>(tA, g1 + 10, tx, ty, o1);
    vpassP<6>(tB, g1 + 10, tx, ty, o2);
    fold(o1, o2, t1a, Sa, false);
    __syncthreads();
    HP_PAIR(11, g2);
    __syncthreads();
    vpassP<11>(tA, g2 + 5, tx, ty, o1);
    vpassP<11>(tB, g2 + 5, tx, ty, o2);
    fold(o1, o2, t1b, Sb, false);
    __syncthreads();
#pragma unroll
    for (int q = 0; q < 3; q++) {
        int idx = tid + q * NT;
        if (idx < 768) hSslot<6>(idx, sx, sy, tAf, g1 + 10);
        else           hSslot<11>(idx - 768, sx, sy, tBf, g2 + 5);
    }
    __syncthreads();
    vpassS<6>(tAf, g1 + 10, tx, ty, exyA);
    vpassS<11>(tBf, g2 + 5, tx, ty, exyB);
    csApply(exyA, t1a, Sa, 1);            // (c1,s1)^1
    csApply(exyB, t1b, Sb, 3);            // (c1,s2)^3
    __syncthreads();
    HP_PAIR(16, g3);
    __syncthreads();
    vpassP<16>(tA, g3, tx, ty, o1);
    vpassP<16>(tB, g3, tx, ty, o2);
    fold(o1, o2, t1a, Sa, false);
    __syncthreads();
#pragma unroll
    for (int q = 0; q < 3; q++)
        hXYslot4(tid + q * NT, sx, sy, tA, g3, g4);   // lone carrierXY(s3)
    __syncthreads();
    vpassXY(tA, g3, g4, tx, ty, o3);
    csApplyCarrier(o3, t1a, Sa, 1);       // (c1,s3)^1 + L1_c1
    __syncthreads();

    // ===================== channel 2 =====================
    loadSlab(2);
    __syncthreads();
    HP_PAIR(16, g3);
    __syncthreads();
    vpassP<16>(tA, g3, tx, ty, o1);
    vpassP<16>(tB, g3, tx, ty, o2);
    fold(o1, o2, t1a, Sa, false);
    __syncthreads();
    HP_PAIR(16, g4);
    __syncthreads();
    vpassP<16>(tA, g4, tx, ty, o1);
    vpassP<16>(tB, g4, tx, ty, o2);
    fold(o1, o2, t1b, Sb, true);          // + l^3
    __syncthreads();
#pragma unroll
    for (int q = 0; q < 3; q++) {
        int idx = tid + q * NT;
        if (idx < 768) hSslot<16>(idx, sx, sy, tAf, g3);
        else           hXYslot(idx - 768, sx, sy, tB, g4, g4);
    }
    __syncthreads();
    vpassS<16>(tAf, g3, tx, ty, exyA);
    vpassXY(tB, g4, g4, tx, ty, o3);
    csApply(exyA, t1a, Sa, 2);            // (c2,s3)^2
    csApplyCarrier(o3, t1b, Sb, 3);       // (c2,s4)^3 + L1_c2
    __syncthreads();

    // ===================== epilogue =====================
    float tsum = 0.0f;
#pragma unroll
    for (int i = 0; i < 8; i++) {
        float ms = 1.0f - prodS[i * NT + tid];
        float mix = 200.0f * (0.025f * ms +
                              0.975f * (l1sS[i * NT + tid] * (1.0f / 3.0f)));
        tsum += mix;
    }

    __syncthreads();
    float* r1 = tAf;
    float* r2 = tAf + NT;
    r1[tid] = tsum;
    r2[tid] = rawL1;
    __syncthreads();
    for (int s = NT / 2; s > 0; s >>= 1) {
        if (tid < s) { r1[tid] += r1[tid + s]; r2[tid] += r2[tid + s]; }
        __syncthreads();
    }
    int bid = (blockIdx.z * 8 + blockIdx.y) * 8 + blockIdx.x;
    if (tid == 0) {
        g_partLoss[bid] = r1[0];
        g_partL1[bid] = r2[0];
    }

    __shared__ int isLast;
    __threadfence();
    if (tid == 0) isLast = (atomicAdd(&g_counter, 1) == NBLK - 1) ? 1 : 0;
    __syncthreads();
    if (!isLast) return;
    __threadfence();

    float ms = 0.0f;
    for (int i = tid; i < ndisc; i += NT) {
        float v = disc[i] - 1.0f;
        ms = fmaf(v, v, ms);
    }
    double s1 = (double)g_partLoss[tid];
    double s2 = (double)g_partL1[tid];

    double* d1 = (double*)tA;
    double* d2 = d1 + NT;
    float* d3 = (float*)(d2 + NT);
    __syncthreads();
    d1[tid] = s1; d2[tid] = s2; d3[tid] = ms;
    __syncthreads();
    for (int s = NT / 2; s > 0; s >>= 1) {
        if (tid < s) {
            d1[tid] += d1[tid + s];
            d2[tid] += d2[tid + s];
            d3[tid] += d3[tid + s];
        }
        __syncthreads();
    }
    if (tid == 0) {
        double lossMixMean = d1[0] / 2097152.0;     // 8*512*512
        double l1Mean = d2[0] / 6291456.0;          // 8*3*512*512
        double mseMean = (double)d3[0] / (double)ndisc;
        out[0] = (float)((lossMixMean + 100.0 * l1Mean + mseMean) * 0.5);
        g_counter = 0;
        __threadfence();
    }
}

// ---------------------------------------------------------------------------
extern "C" void kernel_launch(void* const* d_in, const int* in_sizes, int n_in,
                              void* d_out, int out_size) {
    const float* x = (const float*)d_in[0];
    const float* y = (const float*)d_in[1];
    const float* disc = (const float*)d_in[2];
    int ndisc = in_sizes[2];

    static const float sigmas[5] = {0.5f, 1.0f, 2.0f, 4.0f, 8.0f};
    Coefs cf;
    for (int s = 0; s < 5; s++) {
        float sum = 0.0f;
        for (int i = 0; i < 33; i++) {
            float d = (float)(i - 16);
            float v = expf(-d * d / (2.0f * sigmas[s] * sigmas[s]));
            cf.g[s][i] = v;
            sum += v;
        }
        for (int i = 0; i < 33; i++) cf.g[s][i] /= sum;
    }

    cudaFuncSetAttribute(fusedK, cudaFuncAttributeMaxDynamicSharedMemorySize,
                         SMEM_BYTES);
    fusedK<<<dim3(8, 8, 8), NT, SMEM_BYTES>>>(x, y, disc, ndisc,
                                              (float*)d_out, cf);
}

// round 11
// speedup vs baseline: 1.0788x; 1.0063x over previous
#include <cuda_runtime.h>
#include <math.h>

// ---------------------------------------------------------------------------
// MS-SSIM + L1 loss — R4 base (260us artifact) + phase pairing only.
//
// 3 launches: initCoefs -> fusedK -> finalK (exactly the proven structure;
// coefs in __device__ g_g1d read via __ldg).
//
// fusedK, per 64x64 tile (512 threads, 96x96 slab):
//   paired h-phases (1536 slots = exactly 3/thread, crit 3 vs 2+2):
//     hP x+y of one sigma -> tA/tB       (packed (v,v^2) FFMA2)
//     c1: xy@s1 -> tA  +  xy@s2 -> tB   (scalar)
//     c2: xy@s3 -> tA  +  carrierXY@s4 -> tB  (equal 33-tap)
//     c0: xy@s0 -> tA  +  carrierXY@s1 -> tB  (mixed 7/33-tap, warp-uniform)
//   lone phase: c1 carrierXY@s3 (768 slots, crit 2).
//   v-passes + immediate fold (t1=C2-2*mxy, S=sxx+syy+C2) -> short live ranges.
//   prod/l1s accumulators in REGISTERS (R10's smem accumulators regressed).
// ---------------------------------------------------------------------------

typedef unsigned long long u64;

#define W2 97     // slab row stride (floats); conflict-free
#define WTU 65    // tmp row stride (u64 for packed, float for scalar)
#define NT 512
#define NBLK 512
// tA(96*65 u64=49920B) + tB(49920B) + sx(96*97*4) + sy = 174336 B
#define SMEM_BYTES (2 * 96 * WTU * 8 + 2 * 96 * W2 * 4)

__device__ float g_g1d[5 * 33];
__device__ float g_partLoss[NBLK];
__device__ float g_partL1[NBLK];

__global__ void initCoefs(const float* __restrict__ gm) {
    int t = threadIdx.x;
    if (t < 165) {
        int s = t / 33, i = t % 33;
        g_g1d[t] = sqrtf(fmaxf(gm[(3 * s) * 1089 + i * 34], 0.0f));
    }
}

// ---------------------------------------------------------------------------
__device__ __forceinline__ u64 pk2(float lo, float hi) {
    u64 r; asm("mov.b64 %0, {%1, %2};" : "=l"(r) : "f"(lo), "f"(hi)); return r;
}
__device__ __forceinline__ void upk2(u64 v, float& lo, float& hi) {
    asm("mov.b64 {%0, %1}, %2;" : "=f"(lo), "=f"(hi) : "l"(v));
}
__device__ __forceinline__ u64 ffma2(u64 a, u64 b, u64 c) {
    u64 d; asm("fma.rn.f32x2 %0, %1, %2, %3;" : "=l"(d) : "l"(a), "l"(b), "l"(c));
    return d;
}

// ---------------------------------------------------------------------------
// h slot bodies (grp8: slot in [0,768) = 96 rows x 8 col-groups of 8).

template <int R>
__device__ __forceinline__ void hPslot(int slot, const float* __restrict__ s,
                                       u64* t, const float* __restrict__ g1) {
    int r = slot % 96, gq = slot / 96;
    const float* p = s + r * W2 + gq * 8 + (16 - R);
    u64 acc[8], w[8];
#pragma unroll
    for (int j = 0; j < 8; j++) { float f = p[j]; w[j] = pk2(f, f * f); }
#pragma unroll
    for (int i = 0; i < 8; i++) acc[i] = 0ULL;
#pragma unroll
    for (int k = 0; k <= 2 * R; k++) {
        float gk = __ldg(g1 + k);
        u64 c2 = pk2(gk, gk);
#pragma unroll
        for (int i = 0; i < 8; i++) acc[i] = ffma2(c2, w[(k + i) & 7], acc[i]);
        if (k < 2 * R) { float f = p[k + 8]; w[k & 7] = pk2(f, f * f); }
    }
    u64* ob = t + r * WTU + gq * 8;
#pragma unroll
    for (int i = 0; i < 8; i++) ob[i] = acc[i];
}

template <int R>
__device__ __forceinline__ void hSslot(int slot, const float* sx, const float* sy,
                                       float* t0, const float* __restrict__ g1) {
    int r = slot % 96, gq = slot / 96;
    const float* px = sx + r * W2 + gq * 8 + (16 - R);
    const float* py = sy + r * W2 + gq * 8 + (16 - R);
    float acc[8], w[8];
#pragma unroll
    for (int j = 0; j < 8; j++) w[j] = px[j] * py[j];
#pragma unroll
    for (int i = 0; i < 8; i++) acc[i] = 0.0f;
#pragma unroll
    for (int k = 0; k <= 2 * R; k++) {
        float gk = __ldg(g1 + k);
#pragma unroll
        for (int i = 0; i < 8; i++) acc[i] = fmaf(gk, w[(k + i) & 7], acc[i]);
        if (k < 2 * R) w[k & 7] = px[k + 8] * py[k + 8];
    }
    float* ob = t0 + r * WTU + gq * 8;
#pragma unroll
    for (int i = 0; i < 8; i++) ob[i] = acc[i];
}

__device__ __forceinline__ void hXYslot(int slot, const float* sx, const float* sy,
                                        u64* t, const float* __restrict__ gA,
                                        const float* __restrict__ gB) {
    int r = slot % 96, gq = slot / 96;
    const float* px = sx + r * W2 + gq * 8;
    const float* py = sy + r * W2 + gq * 8;
    u64 acc[8], w[8];
#pragma unroll
    for (int j = 0; j < 8; j++) {
        float xv = px[j], yv = py[j];
        w[j] = pk2(xv * yv, fabsf(xv - yv));
    }
#pragma unroll
    for (int i = 0; i < 8; i++) acc[i] = 0ULL;
#pragma unroll
    for (int k = 0; k <= 32; k++) {
        u64 c2 = pk2(__ldg(gA + k), __ldg(gB + k));
#pragma unroll
        for (int i = 0; i < 8; i++) acc[i] = ffma2(c2, w[(k + i) & 7], acc[i]);
        if (k < 32) {
            float xv = px[k + 8], yv = py[k + 8];
            w[k & 7] = pk2(xv * yv, fabsf(xv - yv));
        }
    }
    u64* ob = t + r * WTU + gq * 8;
#pragma unroll
    for (int i = 0; i < 8; i++) ob[i] = acc[i];
}

// ---------------------------------------------------------------------------
// v passes: 512 threads = 64 cols x 8 row-groups of 8.
template <int R>
__device__ __forceinline__ void vpassP(const u64* t2, const float* __restrict__ g1,
                                       int tx, int ty, u64 out[8]) {
    const u64* p = t2 + (ty * 8 + 16 - R) * WTU + tx;
    u64 acc[8], w[8];
#pragma unroll
    for (int j = 0; j < 8; j++) w[j] = p[j * WTU];
#pragma unroll
    for (int i = 0; i < 8; i++) acc[i] = 0ULL;
#pragma unroll
    for (int k = 0; k <= 2 * R; k++) {
        float gk = __ldg(g1 + k);
        u64 c2 = pk2(gk, gk);
#pragma unroll
        for (int i = 0; i < 8; i++) acc[i] = ffma2(c2, w[(k + i) & 7], acc[i]);
        if (k < 2 * R) w[k & 7] = p[(k + 8) * WTU];
    }
#pragma unroll
    for (int i = 0; i < 8; i++) out[i] = acc[i];
}

__device__ __forceinline__ void vpassXY(const u64* t2,
                                        const float* __restrict__ gA,
                                        const float* __restrict__ gB,
                                        int tx, int ty, u64 out[8]) {
    const u64* p = t2 + ty * 8 * WTU + tx;
    u64 acc[8], w[8];
#pragma unroll
    for (int j = 0; j < 8; j++) w[j] = p[j * WTU];
#pragma unroll
    for (int i = 0; i < 8; i++) acc[i] = 0ULL;
#pragma unroll
    for (int k = 0; k <= 32; k++) {
        u64 c2 = pk2(__ldg(gA + k), __ldg(gB + k));
#pragma unroll
        for (int i = 0; i < 8; i++) acc[i] = ffma2(c2, w[(k + i) & 7], acc[i]);
        if (k < 32) w[k & 7] = p[(k + 8) * WTU];
    }
#pragma unroll
    for (int i = 0; i < 8; i++) out[i] = acc[i];
}

template <int R>
__device__ __forceinline__ void vpassS(const float* t0, const float* __restrict__ g1,
                                       int tx, int ty, float out[8]) {
    const float* p = t0 + (ty * 8 + 16 - R) * WTU + tx;
    float acc[8], w[8];
#pragma unroll
    for (int j = 0; j < 8; j++) w[j] = p[j * WTU];
#pragma unroll
    for (int i = 0; i < 8; i++) acc[i] = 0.0f;
#pragma unroll
    for (int k = 0; k <= 2 * R; k++) {
        float gk = __ldg(g1 + k);
#pragma unroll
        for (int i = 0; i < 8; i++) acc[i] = fmaf(gk, w[(k + i) & 7], acc[i]);
        if (k < 2 * R) w[k & 7] = p[(k + 8) * WTU];
    }
#pragma unroll
    for (int i = 0; i < 8; i++) out[i] = acc[i];
}

// ---------------------------------------------------------------------------
__global__ __launch_bounds__(NT) void fusedK(const float* __restrict__ x,
                                             const float* __restrict__ y) {
    extern __shared__ float smem[];
    u64* tA = (u64*)smem;                 // 96 x WTU u64
    u64* tB = tA + 96 * WTU;
    float* tAf = (float*)tA;
    float* tBf = (float*)tB;
    float* sx = (float*)(tB + 96 * WTU);  // 96 x W2
    float* sy = sx + 96 * W2;

    int tid = threadIdx.x;
    int tx = tid & 63, ty = tid >> 6;
    int col0 = blockIdx.x * 64, row0 = blockIdx.y * 64, b = blockIdx.z;

    const float* g0 = g_g1d;
    const float* g1 = g_g1d + 33;
    const float* g2 = g_g1d + 66;
    const float* g3 = g_g1d + 99;
    const float* g4 = g_g1d + 132;

    float prod[8], l1s[8];
#pragma unroll
    for (int i = 0; i < 8; i++) { prod[i] = 1.0f; l1s[i] = 0.0f; }
    float rawL1 = 0.0f;

    float t1a[8], Sa[8], t1b[8], Sb[8];
    u64 o1[8], o2[8], o3[8];
    float exyA[8], exyB[8];

    auto fold = [&](const u64* ox, const u64* oy, float* t1, float* S, bool lm) {
#pragma unroll
        for (int i = 0; i < 8; i++) {
            float mux, ex2, muy, ey2;
            upk2(ox[i], mux, ex2);
            upk2(oy[i], muy, ey2);
            float m2x = mux * mux, m2y = muy * muy, mxy = mux * muy;
            t1[i] = 9.0e-4f - 2.0f * mxy;
            S[i] = (ex2 - m2x) + (ey2 - m2y) + 9.0e-4f;
            if (lm) {
                float l = __fdividef(2.0f * mxy + 1.0e-4f, m2x + m2y + 1.0e-4f);
                prod[i] *= l * l * l;
            }
        }
    };
    auto csApply = [&](const float* e, const float* t1, const float* S, int mult) {
#pragma unroll
        for (int i = 0; i < 8; i++) {
            float cs = __fdividef(2.0f * e[i] + t1[i], S[i]);
            float m = cs;
            if (mult >= 2) m *= cs;
            if (mult >= 3) m *= cs;
            prod[i] *= m;
        }
    };
    auto csApplyCarrier = [&](const u64* o, const float* t1, const float* S,
                              int mult) {
#pragma unroll
        for (int i = 0; i < 8; i++) {
            float e, lv;
            upk2(o[i], e, lv);
            l1s[i] += lv;
            float cs = __fdividef(2.0f * e + t1[i], S[i]);
            float m = cs;
            if (mult >= 2) m *= cs;
            if (mult >= 3) m *= cs;
            prod[i] *= m;
        }
    };

    auto loadSlab = [&](int c) {
        const float* xp = x + (size_t)(b * 3 + c) * 262144;
        const float* yp = y + (size_t)(b * 3 + c) * 262144;
        for (int idx = tid; idx < 96 * 96; idx += NT) {
            int rr = idx / 96, cc = idx - rr * 96;
            int gr = row0 - 16 + rr, gc = col0 - 16 + cc;
            float xv = 0.0f, yv = 0.0f;
            if (gr >= 0 && gr < 512 && gc >= 0 && gc < 512) {
                xv = fmaf(xp[gr * 512 + gc], 0.5f, 0.5f);
                yv = fmaf(yp[gr * 512 + gc], 0.5f, 0.5f);
            }
            sx[rr * W2 + cc] = xv;
            sy[rr * W2 + cc] = yv;
            if (rr >= 16 && rr < 80 && cc >= 16 && cc < 80)
                rawL1 += fabsf(xv - yv);
        }
    };

    // Paired hP phase: x -> tA, y -> tB (1536 slots, exactly 3/thread).
#define HP_PAIR(R, GG)                                                       \
    do {                                                                     \
        _Pragma("unroll")                                                    \
        for (int q = 0; q < 3; q++) {                                        \
            int idx = tid + q * NT;                                          \
            if (idx < 768) hPslot<R>(idx, sx, tA, (GG) + (16 - (R)));        \
            else           hPslot<R>(idx - 768, sy, tB, (GG) + (16 - (R)));  \
        }                                                                    \
    } while (0)

    // ===================== channel 0 =====================
    loadSlab(0);
    __syncthreads();
    HP_PAIR(3, g0);
    __syncthreads();
    vpassP<3>(tA, g0 + 13, tx, ty, o1);
    vpassP<3>(tB, g0 + 13, tx, ty, o2);
    fold(o1, o2, t1a, Sa, false);                 // s0 @ c0
    __syncthreads();
    HP_PAIR(6, g1);
    __syncthreads();
    vpassP<6>(tA, g1 + 10, tx, ty, o1);
    vpassP<6>(tB, g1 + 10, tx, ty, o2);
    fold(o1, o2, t1b, Sb, false);                 // s1 @ c0
    __syncthreads();
    // mixed phase: xy@s0 (t7) -> tAf ; carrierXY@s1 (t33) -> tB
#pragma unroll
    for (int q = 0; q < 3; q++) {
        int idx = tid + q * NT;
        if (idx < 768) hSslot<3>(idx, sx, sy, tAf, g0 + 13);
        else           hXYslot(idx - 768, sx, sy, tB, g1, g4);
    }
    __syncthreads();
    vpassS<3>(tAf, g0 + 13, tx, ty, exyA);
    vpassXY(tB, g1, g4, tx, ty, o3);
    csApply(exyA, t1a, Sa, 3);                    // (c0,s0)^3
    csApplyCarrier(o3, t1b, Sb, 2);               // (c0,s1)^2 + L1_c0
    __syncthreads();

    // ===================== channel 1 =====================
    loadSlab(1);
    __syncthreads();
    HP_PAIR(6, g1);
    __syncthreads();
    vpassP<6>(tA, g1 + 10, tx, ty, o1);
    vpassP<6>(tB, g1 + 10, tx, ty, o2);
    fold(o1, o2, t1a, Sa, false);                 // s1 @ c1
    __syncthreads();
    HP_PAIR(11, g2);
    __syncthreads();
    vpassP<11>(tA, g2 + 5, tx, ty, o1);
    vpassP<11>(tB, g2 + 5, tx, ty, o2);
    fold(o1, o2, t1b, Sb, false);                 // s2 @ c1
    __syncthreads();
    // paired scalar: xy@s1 -> tAf ; xy@s2 -> tBf
#pragma unroll
    for (int q = 0; q < 3; q++) {
        int idx = tid + q * NT;
        if (idx < 768) hSslot<6>(idx, sx, sy, tAf, g1 + 10);
        else           hSslot<11>(idx - 768, sx, sy, tBf, g2 + 5);
    }
    __syncthreads();
    vpassS<6>(tAf, g1 + 10, tx, ty, exyA);
    vpassS<11>(tBf, g2 + 5, tx, ty, exyB);
    csApply(exyA, t1a, Sa, 1);                    // (c1,s1)^1
    csApply(exyB, t1b, Sb, 3);                    // (c1,s2)^3
    __syncthreads();
    HP_PAIR(16, g3);
    __syncthreads();
    vpassP<16>(tA, g3, tx, ty, o1);
    vpassP<16>(tB, g3, tx, ty, o2);
    fold(o1, o2, t1a, Sa, false);                 // s3 @ c1
    __syncthreads();
    // lone carrierXY@s3 (768 slots, crit 2)
#pragma unroll
    for (int q = 0; q < 2; q++) {
        int idx = tid + q * NT;
        if (idx < 768) hXYslot(idx, sx, sy, tA, g3, g4);
    }
    __syncthreads();
    vpassXY(tA, g3, g4, tx, ty, o3);
    csApplyCarrier(o3, t1a, Sa, 1);               // (c1,s3)^1 + L1_c1
    __syncthreads();

    // ===================== channel 2 =====================
    loadSlab(2);
    __syncthreads();
    HP_PAIR(16, g3);
    __syncthreads();
    vpassP<16>(tA, g3, tx, ty, o1);
    vpassP<16>(tB, g3, tx, ty, o2);
    fold(o1, o2, t1a, Sa, false);                 // s3 @ c2
    __syncthreads();
    HP_PAIR(16, g4);
    __syncthreads();
    vpassP<16>(tA, g4, tx, ty, o1);
    vpassP<16>(tB, g4, tx, ty, o2);
    fold(o1, o2, t1b, Sb, true);                  // s4 @ c2 + l^3
    __syncthreads();
    // paired equal-tap: xy@s3 -> tAf ; carrierXY@s4 -> tB
#pragma unroll
    for (int q = 0; q < 3; q++) {
        int idx = tid + q * NT;
        if (idx < 768) hSslot<16>(idx, sx, sy, tAf, g3);
        else           hXYslot(idx - 768, sx, sy, tB, g4, g4);
    }
    __syncthreads();
    vpassS<16>(tAf, g3, tx, ty, exyA);
    vpassXY(tB, g4, g4, tx, ty, o3);
    csApply(exyA, t1a, Sa, 2);                    // (c2,s3)^2
    csApplyCarrier(o3, t1b, Sb, 3);               // (c2,s4)^3 + L1_c2
    __syncthreads();

    // ===================== epilogue =====================
    float tsum = 0.0f;
#pragma unroll
    for (int i = 0; i < 8; i++) {
        float ms = 1.0f - prod[i];
        float mix = 200.0f * (0.025f * ms + 0.975f * (l1s[i] * (1.0f / 3.0f)));
        tsum += mix;
    }

    float* r1 = tAf;
    float* r2 = tAf + NT;
    r1[tid] = tsum;
    r2[tid] = rawL1;
    __syncthreads();
    for (int s = NT / 2; s > 0; s >>= 1) {
        if (tid < s) { r1[tid] += r1[tid + s]; r2[tid] += r2[tid + s]; }
        __syncthreads();
    }
    if (tid == 0) {
        int bid = (blockIdx.z * 8 + blockIdx.y) * 8 + blockIdx.x;
        g_partLoss[bid] = r1[0];
        g_partL1[bid] = r2[0];
    }
}

// ---------------------------------------------------------------------------
__global__ void finalK(float* out, const float* __restrict__ disc, int ndisc) {
    int tid = threadIdx.x;
    float ms = 0.0f;
    for (int i = tid; i < ndisc; i += 256) {
        float v = disc[i] - 1.0f;
        ms = fmaf(v, v, ms);
    }
    double s1 = 0.0, s2 = 0.0;
    for (int i = tid; i < NBLK; i += 256) {
        s1 += (double)g_partLoss[i];
        s2 += (double)g_partL1[i];
    }
    __shared__ double r1[256], r2[256];
    __shared__ float r3[256];
    r1[tid] = s1; r2[tid] = s2; r3[tid] = ms;
    __syncthreads();
    for (int s = 128; s > 0; s >>= 1) {
        if (tid < s) {
            r1[tid] += r1[tid + s];
            r2[tid] += r2[tid + s];
            r3[tid] += r3[tid + s];
        }
        __syncthreads();
    }
    if (tid == 0) {
        double lossMixMean = r1[0] / 2097152.0;     // 8*512*512
        double l1Mean = r2[0] / 6291456.0;          // 8*3*512*512
        double mseMean = (double)r3[0] / (double)ndisc;
        out[0] = (float)((lossMixMean + 100.0 * l1Mean + mseMean) * 0.5);
    }
}

// ---------------------------------------------------------------------------
extern "C" void kernel_launch(void* const* d_in, const int* in_sizes, int n_in,
                              void* d_out, int out_size) {
    const float* x = (const float*)d_in[0];
    const float* y = (const float*)d_in[1];
    const float* disc = (const float*)d_in[2];
    const float* gm = (const float*)d_in[3];
    int ndisc = in_sizes[2];

    cudaFuncSetAttribute(fusedK, cudaFuncAttributeMaxDynamicSharedMemorySize,
                         SMEM_BYTES);
    initCoefs<<<1, 192>>>(gm);
    fusedK<<<dim3(8, 8, 8), NT, SMEM_BYTES>>>(x, y);
    finalK<<<1, 256>>>((float*)d_out, disc, ndisc);
}

// round 14
// speedup vs baseline: 1.2532x; 1.1616x over previous
#include <cuda_runtime.h>
#include <math.h>

// ---------------------------------------------------------------------------
// MS-SSIM + L1 loss — champion (260us) structure with compile-time-immediate
// Gaussian coefficients.
//
// Coefs: sigmas {0.5,1,2,4,8} are fixed; a constexpr exp computes each
// normalized 1-D tap at COMPILE TIME (flushing sub-FLT_MIN tails to 0.0f,
// exactly matching the reference's float32 mask build) and template-recursive
// tap loops bake them as literals -> packed paths use MOV-imm + FFMA2
// (no LDG), scalar paths use FFMA-imm (rt=1). Zero coefficient memory traffic.
//
// Everything else is the proven 260us kernel verbatim: per 64x64 tile
// (512 thr, 96x96 slab), per (channel,sigma) combo:
//   hP(x)->sync->vP->sync->hP(y)->sync->vP->sync->{carrierXY | scalar xy}
//   packed (v,v^2) FFMA2 convs; carrier = (x*y,|x-y|) dual conv;
//   immediate fold, prod/l1s in registers; block reduce -> partials.
// finalK: disc MSE + deterministic combine. 2 launches.
// ---------------------------------------------------------------------------

typedef unsigned long long u64;

#define W2 97     // slab row stride (floats); conflict-free
#define WTU 65    // tmp row stride (u64 packed / float scalar)
#define NT 512
#define NBLK 512
#define SMEM_BYTES (2 * 96 * W2 * 4 + 96 * WTU * 8)   // 124416

__device__ float g_partLoss[NBLK];
__device__ float g_partL1[NBLK];

// ------------------------- compile-time Gaussian ---------------------------
__host__ __device__ constexpr double cexp(double x) {
    // x <= 0. exp(x) = 2^n * e^r, r in [0, ln2).
    constexpr double LN2 = 0.6931471805599453;
    double q = x / LN2;
    long long n = (long long)q;
    if ((double)n > q) n -= 1;
    double r = x - (double)n * LN2;
    double t = 1.0, sm = 1.0;
    for (int i = 1; i <= 20; i++) { t *= r / (double)i; sm += t; }
    for (long long i = 0; i > n; i--) sm *= 0.5;
    return sm;
}
__host__ __device__ constexpr double sigOf(int s) {
    return s == 0 ? 0.5 : s == 1 ? 1.0 : s == 2 ? 2.0 : s == 3 ? 4.0 : 8.0;
}
__host__ __device__ constexpr double gsum(double sig) {
    double s = 0.0;
    for (int i = 0; i < 33; i++) {
        double d = (double)(i - 16);
        s += cexp(-d * d / (2.0 * sig * sig));
    }
    return s;
}
// Normalized tap; flush values below FLT_MIN to 0 (reference builds masks in
// float32, where these tails underflow to exactly 0 as well).
__host__ __device__ constexpr float gcoef(int s, int k) {
    double sig = sigOf(s);
    double d = (double)(k - 16);
    double v = cexp(-d * d / (2.0 * sig * sig)) / gsum(sig);
    return (v < 1.2e-38) ? 0.0f : (float)v;
}
template <int S, int K>
struct GC { static constexpr float v = gcoef(S, K); };

// ---------------------------------------------------------------------------
__device__ __forceinline__ u64 pk2(float lo, float hi) {
    u64 r; asm("mov.b64 %0, {%1, %2};" : "=l"(r) : "f"(lo), "f"(hi)); return r;
}
__device__ __forceinline__ void upk2(u64 v, float& lo, float& hi) {
    asm("mov.b64 {%0, %1}, %2;" : "=f"(lo), "=f"(hi) : "l"(v));
}
__device__ __forceinline__ u64 ffma2(u64 a, u64 b, u64 c) {
    u64 d; asm("fma.rn.f32x2 %0, %1, %2, %3;" : "=l"(d) : "l"(a), "l"(b), "l"(c));
    return d;
}

// ------------------------- h slot bodies (grp8) ----------------------------
// Packed (v, v^2), immediate coefs.
template <int S, int R, int K>
__device__ __forceinline__ void tapP(const float* __restrict__ p,
                                     u64 (&w)[8], u64 (&acc)[8]) {
    if constexpr (K <= 2 * R) {
        constexpr float gk = GC<S, 16 - R + K>::v;
        u64 c2 = pk2(gk, gk);
#pragma unroll
        for (int i = 0; i < 8; i++) acc[i] = ffma2(c2, w[(K + i) & 7], acc[i]);
        if constexpr (K < 2 * R) { float f = p[K + 8]; w[K & 7] = pk2(f, f * f); }
        tapP<S, R, K + 1>(p, w, acc);
    }
}
template <int S, int R>
__device__ __forceinline__ void hPslot(int slot, const float* __restrict__ s, u64* t) {
    int r = slot % 96, gq = slot / 96;
    const float* p = s + r * W2 + gq * 8 + (16 - R);
    u64 acc[8], w[8];
#pragma unroll
    for (int j = 0; j < 8; j++) { float f = p[j]; w[j] = pk2(f, f * f); }
#pragma unroll
    for (int i = 0; i < 8; i++) acc[i] = 0ULL;
    tapP<S, R, 0>(p, w, acc);
    u64* ob = t + r * WTU + gq * 8;
#pragma unroll
    for (int i = 0; i < 8; i++) ob[i] = acc[i];
}

// Scalar xy, immediate coefs (FFMA-imm).
template <int S, int R, int K>
__device__ __forceinline__ void tapS(const float* __restrict__ px,
                                     const float* __restrict__ py,
                                     float (&w)[8], float (&acc)[8]) {
    if constexpr (K <= 2 * R) {
        constexpr float gk = GC<S, 16 - R + K>::v;
#pragma unroll
        for (int i = 0; i < 8; i++) acc[i] = fmaf(gk, w[(K + i) & 7], acc[i]);
        if constexpr (K < 2 * R) w[K & 7] = px[K + 8] * py[K + 8];
        tapS<S, R, K + 1>(px, py, w, acc);
    }
}
template <int S, int R>
__device__ __forceinline__ void hSslot(int slot, const float* sx, const float* sy,
                                       float* t0) {
    int r = slot % 96, gq = slot / 96;
    const float* px = sx + r * W2 + gq * 8 + (16 - R);
    const float* py = sy + r * W2 + gq * 8 + (16 - R);
    float acc[8], w[8];
#pragma unroll
    for (int j = 0; j < 8; j++) w[j] = px[j] * py[j];
#pragma unroll
    for (int i = 0; i < 8; i++) acc[i] = 0.0f;
    tapS<S, R, 0>(px, py, w, acc);
    float* ob = t0 + r * WTU + gq * 8;
#pragma unroll
    for (int i = 0; i < 8; i++) ob[i] = acc[i];
}

// Packed (x*y, |x-y|) dual conv, full 33 taps, per-lane immediate coefs.
template <int SA, int K>
__device__ __forceinline__ void tapXY(const float* __restrict__ px,
                                      const float* __restrict__ py,
                                      u64 (&w)[8], u64 (&acc)[8]) {
    if constexpr (K <= 32) {
        constexpr float ga = GC<SA, K>::v;
        constexpr float gb = GC<4, K>::v;
        u64 c2 = pk2(ga, gb);
#pragma unroll
        for (int i = 0; i < 8; i++) acc[i] = ffma2(c2, w[(K + i) & 7], acc[i]);
        if constexpr (K < 32) {
            float xv = px[K + 8], yv = py[K + 8];
            w[K & 7] = pk2(xv * yv, fabsf(xv - yv));
        }
        tapXY<SA, K + 1>(px, py, w, acc);
    }
}
template <int SA>
__device__ __forceinline__ void hXYslot(int slot, const float* sx, const float* sy,
                                        u64* t) {
    int r = slot % 96, gq = slot / 96;
    const float* px = sx + r * W2 + gq * 8;
    const float* py = sy + r * W2 + gq * 8;
    u64 acc[8], w[8];
#pragma unroll
    for (int j = 0; j < 8; j++) {
        float xv = px[j], yv = py[j];
        w[j] = pk2(xv * yv, fabsf(xv - yv));
    }
#pragma unroll
    for (int i = 0; i < 8; i++) acc[i] = 0ULL;
    tapXY<SA, 0>(px, py, w, acc);
    u64* ob = t + r * WTU + gq * 8;
#pragma unroll
    for (int i = 0; i < 8; i++) ob[i] = acc[i];
}

// ------------------------- v passes (64 cols x 8 row-groups) ---------------
template <int S, int R, int K>
__device__ __forceinline__ void vtapP(const u64* __restrict__ p,
                                      u64 (&w)[8], u64 (&acc)[8]) {
    if constexpr (K <= 2 * R) {
        constexpr float gk = GC<S, 16 - R + K>::v;
        u64 c2 = pk2(gk, gk);
#pragma unroll
        for (int i = 0; i < 8; i++) acc[i] = ffma2(c2, w[(K + i) & 7], acc[i]);
        if constexpr (K < 2 * R) w[K & 7] = p[(K + 8) * WTU];
        vtapP<S, R, K + 1>(p, w, acc);
    }
}
template <int S, int R>
__device__ __forceinline__ void vpassP(const u64* t2, int tx, int ty, u64 (&out)[8]) {
    const u64* p = t2 + (ty * 8 + 16 - R) * WTU + tx;
    u64 acc[8], w[8];
#pragma unroll
    for (int j = 0; j < 8; j++) w[j] = p[j * WTU];
#pragma unroll
    for (int i = 0; i < 8; i++) acc[i] = 0ULL;
    vtapP<S, R, 0>(p, w, acc);
#pragma unroll
    for (int i = 0; i < 8; i++) out[i] = acc[i];
}

template <int SA, int K>
__device__ __forceinline__ void vtapXY(const u64* __restrict__ p,
                                       u64 (&w)[8], u64 (&acc)[8]) {
    if constexpr (K <= 32) {
        constexpr float ga = GC<SA, K>::v;
        constexpr float gb = GC<4, K>::v;
        u64 c2 = pk2(ga, gb);
#pragma unroll
        for (int i = 0; i < 8; i++) acc[i] = ffma2(c2, w[(K + i) & 7], acc[i]);
        if constexpr (K < 32) w[K & 7] = p[(K + 8) * WTU];
        vtapXY<SA, K + 1>(p, w, acc);
    }
}
template <int SA>
__device__ __forceinline__ void vpassXY(const u64* t2, int tx, int ty, u64 (&out)[8]) {
    const u64* p = t2 + ty * 8 * WTU + tx;
    u64 acc[8], w[8];
#pragma unroll
    for (int j = 0; j < 8; j++) w[j] = p[j * WTU];
#pragma unroll
    for (int i = 0; i < 8; i++) acc[i] = 0ULL;
    vtapXY<SA, 0>(p, w, acc);
#pragma unroll
    for (int i = 0; i < 8; i++) out[i] = acc[i];
}

template <int S, int R, int K>
__device__ __forceinline__ void vtapS(const float* __restrict__ p,
                                      float (&w)[8], float (&acc)[8]) {
    if constexpr (K <= 2 * R) {
        constexpr float gk = GC<S, 16 - R + K>::v;
#pragma unroll
        for (int i = 0; i < 8; i++) acc[i] = fmaf(gk, w[(K + i) & 7], acc[i]);
        if constexpr (K < 2 * R) w[K & 7] = p[(K + 8) * WTU];
        vtapS<S, R, K + 1>(p, w, acc);
    }
}
template <int S, int R>
__device__ __forceinline__ void vpassS(const float* t0, int tx, int ty,
                                       float (&out)[8]) {
    const float* p = t0 + (ty * 8 + 16 - R) * WTU + tx;
    float acc[8], w[8];
#pragma unroll
    for (int j = 0; j < 8; j++) w[j] = p[j * WTU];
#pragma unroll
    for (int i = 0; i < 8; i++) acc[i] = 0.0f;
    vtapS<S, R, 0>(p, w, acc);
#pragma unroll
    for (int i = 0; i < 8; i++) out[i] = acc[i];
}

// ---------------------------------------------------------------------------
template <int S, int R, bool CARRIER>
__device__ __forceinline__ void comboP(int mult, bool lm,
                                       const float* sx, const float* sy,
                                       u64* t2, int tid, int tx, int ty,
                                       float (&prod)[8], float (&l1s)[8]) {
    u64 o1[8], o2[8];
    float exy[8];

    for (int idx = tid; idx < 768; idx += NT) hPslot<S, R>(idx, sx, t2);
    __syncthreads();
    vpassP<S, R>(t2, tx, ty, o1);
    __syncthreads();
    for (int idx = tid; idx < 768; idx += NT) hPslot<S, R>(idx, sy, t2);
    __syncthreads();
    vpassP<S, R>(t2, tx, ty, o2);
    __syncthreads();

    if constexpr (CARRIER) {
        u64 o3[8];
        for (int idx = tid; idx < 768; idx += NT) hXYslot<S>(idx, sx, sy, t2);
        __syncthreads();
        vpassXY<S>(t2, tx, ty, o3);
        __syncthreads();
#pragma unroll
        for (int i = 0; i < 8; i++) {
            float lv;
            upk2(o3[i], exy[i], lv);
            l1s[i] += lv;
        }
    } else {
        float* t0 = (float*)t2;
        for (int idx = tid; idx < 768; idx += NT) hSslot<S, R>(idx, sx, sy, t0);
        __syncthreads();
        vpassS<S, R>(t0, tx, ty, exy);
        __syncthreads();
    }

#pragma unroll
    for (int i = 0; i < 8; i++) {
        float mux, ex2, muy, ey2;
        upk2(o1[i], mux, ex2);
        upk2(o2[i], muy, ey2);
        float m2x = mux * mux, m2y = muy * muy, mxy = mux * muy;
        float sxx = ex2 - m2x, syy = ey2 - m2y, sxyv = exy[i] - mxy;
        float cs = __fdividef(2.0f * sxyv + 9.0e-4f, sxx + syy + 9.0e-4f);
        float m = cs;
        if (mult >= 2) m *= cs;
        if (mult >= 3) m *= cs;
        if (lm) {
            float l = __fdividef(2.0f * mxy + 1.0e-4f, m2x + m2y + 1.0e-4f);
            m *= l * l * l;
        }
        prod[i] *= m;
    }
}

// ---------------------------------------------------------------------------
__global__ __launch_bounds__(NT) void fusedK(const float* __restrict__ x,
                                             const float* __restrict__ y) {
    extern __shared__ float smem[];
    float* sx = smem;                    // 96 x W2
    float* sy = sx + 96 * W2;
    u64* t2 = (u64*)(sy + 96 * W2);      // 96 x WTU u64

    int tid = threadIdx.x;
    int tx = tid & 63, ty = tid >> 6;
    int col0 = blockIdx.x * 64, row0 = blockIdx.y * 64, b = blockIdx.z;

    float prod[8], l1s[8];
#pragma unroll
    for (int i = 0; i < 8; i++) { prod[i] = 1.0f; l1s[i] = 0.0f; }
    float rawL1 = 0.0f;

    for (int c = 0; c < 3; c++) {
        const float* xp = x + (size_t)(b * 3 + c) * 262144;
        const float* yp = y + (size_t)(b * 3 + c) * 262144;
        __syncthreads();
        for (int idx = tid; idx < 96 * 96; idx += NT) {
            int rr = idx / 96, cc = idx - rr * 96;
            int gr = row0 - 16 + rr, gc = col0 - 16 + cc;
            float xv = 0.0f, yv = 0.0f;
            if (gr >= 0 && gr < 512 && gc >= 0 && gc < 512) {
                xv = fmaf(xp[gr * 512 + gc], 0.5f, 0.5f);
                yv = fmaf(yp[gr * 512 + gc], 0.5f, 0.5f);
            }
            sx[rr * W2 + cc] = xv;
            sy[rr * W2 + cc] = yv;
            if (rr >= 16 && rr < 80 && cc >= 16 && cc < 80)
                rawL1 += fabsf(xv - yv);
        }
        __syncthreads();

        if (c == 0) {
            comboP<0, 3, false>(3, false, sx, sy, t2, tid, tx, ty, prod, l1s);
            comboP<1, 6, true>(2, false, sx, sy, t2, tid, tx, ty, prod, l1s);
        } else if (c == 1) {
            comboP<1, 6, false>(1, false, sx, sy, t2, tid, tx, ty, prod, l1s);
            comboP<2, 11, false>(3, false, sx, sy, t2, tid, tx, ty, prod, l1s);
            comboP<3, 16, true>(1, false, sx, sy, t2, tid, tx, ty, prod, l1s);
        } else {
            comboP<3, 16, false>(2, false, sx, sy, t2, tid, tx, ty, prod, l1s);
            comboP<4, 16, true>(3, true, sx, sy, t2, tid, tx, ty, prod, l1s);
        }
    }

    float tsum = 0.0f;
#pragma unroll
    for (int i = 0; i < 8; i++) {
        float ms = 1.0f - prod[i];
        float mix = 200.0f * (0.025f * ms + 0.975f * (l1s[i] * (1.0f / 3.0f)));
        tsum += mix;
    }

    // Block reduction into partials.
    __syncthreads();
    float* r1 = (float*)t2;
    float* r2 = r1 + NT;
    r1[tid] = tsum;
    r2[tid] = rawL1;
    __syncthreads();
    for (int s = NT / 2; s > 0; s >>= 1) {
        if (tid < s) { r1[tid] += r1[tid + s]; r2[tid] += r2[tid + s]; }
        __syncthreads();
    }
    if (tid == 0) {
        int bid = (blockIdx.z * 8 + blockIdx.y) * 8 + blockIdx.x;
        g_partLoss[bid] = r1[0];
        g_partL1[bid] = r2[0];
    }
}

// ---------------------------------------------------------------------------
__global__ void finalK(float* out, const float* __restrict__ disc, int ndisc) {
    int tid = threadIdx.x;
    float ms = 0.0f;
    for (int i = tid; i < ndisc; i += 256) {
        float v = disc[i] - 1.0f;
        ms = fmaf(v, v, ms);
    }
    double s1 = 0.0, s2 = 0.0;
    for (int i = tid; i < NBLK; i += 256) {
        s1 += (double)g_partLoss[i];
        s2 += (double)g_partL1[i];
    }
    __shared__ double r1[256], r2[256];
    __shared__ float r3[256];
    r1[tid] = s1; r2[tid] = s2; r3[tid] = ms;
    __syncthreads();
    for (int s = 128; s > 0; s >>= 1) {
        if (tid < s) {
            r1[tid] += r1[tid + s];
            r2[tid] += r2[tid + s];
            r3[tid] += r3[tid + s];
        }
        __syncthreads();
    }
    if (tid == 0) {
        double lossMixMean = r1[0] / 2097152.0;     // 8*512*512
        double l1Mean = r2[0] / 6291456.0;          // 8*3*512*512
        double mseMean = (double)r3[0] / (double)ndisc;
        out[0] = (float)((lossMixMean + 100.0 * l1Mean + mseMean) * 0.5);
    }
}

// ---------------------------------------------------------------------------
extern "C" void kernel_launch(void* const* d_in, const int* in_sizes, int n_in,
                              void* d_out, int out_size) {
    const float* x = (const float*)d_in[0];
    const float* y = (const float*)d_in[1];
    const float* disc = (const float*)d_in[2];
    int ndisc = in_sizes[2];

    cudaFuncSetAttribute(fusedK, cudaFuncAttributeMaxDynamicSharedMemorySize,
                         SMEM_BYTES);
    fusedK<<<dim3(8, 8, 8), NT, SMEM_BYTES>>>(x, y);
    finalK<<<1, 256>>>((float*)d_out, disc, ndisc);
}